// round 2
// baseline (speedup 1.0000x reference)
#include <cuda_runtime.h>
#include <math.h>

#define CC 128
#define MID 8
#define SB 32      // blocks per spatial dim
#define SPD 64     // full spatial dim

#define TWO_SQRT2 2.8284271247461903f

// scratch (allocation-free rule: __device__ globals)
__device__ float g_part[2 * CC * 8];           // partial corner sums
__device__ float g_gmod[2 * CC];               // global-MLP output
__device__ float g_gate[2 * CC * SB * SB * SB]; // sigmoid gates (33.5 MB, L2-resident)

// ---------------------------------------------------------------------------
// Kernel 1: partial corner sums. 2048 CTAs: (b,c) x 8 d-slices of 4 blocks.
// Deterministic: fixed partial structure, reduced in k_gmlp.
// ---------------------------------------------------------------------------
__global__ __launch_bounds__(256) void k_gap(const float* __restrict__ x) {
    int bc    = blockIdx.x >> 3;     // 0..255
    int slice = blockIdx.x & 7;      // 0..7  (4 d-blocks each)
    const float* base = x + (size_t)bc * (SPD * SPD * SPD)
                          + (size_t)(8 * slice) * SPD * SPD;  // d = 2*(4*slice)
    float sum = 0.f;
    // 4 d-blocks x 32 h x 32 w = 4096 corners, 16 per thread
    for (int i = threadIdx.x; i < 4 * SB * SB; i += 256) {
        int d = i >> 10;             // 0..3
        int h = (i >> 5) & 31;
        int w = i & 31;
        sum += base[((size_t)(2 * d) * SPD + (2 * h)) * SPD + 2 * w];
    }
    __shared__ float red[256];
    red[threadIdx.x] = sum;
    __syncthreads();
    for (int s = 128; s > 0; s >>= 1) {
        if (threadIdx.x < s) red[threadIdx.x] += red[threadIdx.x + s];
        __syncthreads();
    }
    if (threadIdx.x == 0) g_part[bc * 8 + slice] = red[0];
}

// ---------------------------------------------------------------------------
// Kernel 2: reduce partials -> gap, then global MLP -> g_gmod.
// one CTA per batch, 128 threads
// ---------------------------------------------------------------------------
__global__ __launch_bounds__(128) void k_gmlp(const float* __restrict__ gw1,
                                              const float* __restrict__ gb1,
                                              const float* __restrict__ gw2,
                                              const float* __restrict__ gb2) {
    int b = blockIdx.x;
    int t = threadIdx.x;  // 0..127
    __shared__ float gap_s[CC];
    __shared__ float hid[MID];
    {
        float s = 0.f;
        #pragma unroll
        for (int i = 0; i < 8; i++) s += g_part[(b * CC + t) * 8 + i];
        gap_s[t] = s * (TWO_SQRT2 / 32768.0f);
    }
    __syncthreads();
    if (t < MID) {
        float a = gb1[t];
        #pragma unroll 8
        for (int c = 0; c < CC; c++) a += gw1[t * CC + c] * gap_s[c];
        hid[t] = fmaxf(a, 0.f);
    }
    __syncthreads();
    float a = gb2[t];
    #pragma unroll
    for (int m = 0; m < MID; m++) a += gw2[t * MID + m] * hid[m];
    g_gmod[b * CC + t] = a;
}

// ---------------------------------------------------------------------------
// Kernel 3: per (b, d, h) CTA — local MLP over 128 channels x 32 w-blocks,
// write sigmoid gates to g_gate (L2-resident for the blend kernel).
// ---------------------------------------------------------------------------
__global__ __launch_bounds__(256) void k_gate(const float* __restrict__ x,
                                              const float* __restrict__ lw1,
                                              const float* __restrict__ lb1,
                                              const float* __restrict__ lw2,
                                              const float* __restrict__ lb2) {
    int bid = blockIdx.x;          // 0..2047
    int b = bid >> 10;
    int d = (bid >> 5) & 31;
    int h = bid & 31;
    int t = threadIdx.x;

    __shared__ float s_s[CC][SB];      // x_sum values
    __shared__ float s_hid[MID][SB];
    __shared__ float s_lw1[MID * CC];
    __shared__ float s_lw2[CC * MID];
    __shared__ float s_g[CC];
    __shared__ float s_lb2[CC];

    for (int i = t; i < MID * CC; i += 256) s_lw1[i] = lw1[i];
    for (int i = t; i < CC * MID; i += 256) s_lw2[i] = lw2[i];
    if (t < CC) {
        s_g[t]   = g_gmod[b * CC + t];
        s_lb2[t] = lb2[t];
    }

    const float* xb = x + (size_t)b * CC * SPD * SPD * SPD;

    // corners (likely L2 hits from k_gap): 128 channels x 32 w-blocks
    for (int i = t; i < CC * SB; i += 256) {
        int c = i >> 5;
        int w = i & 31;
        s_s[c][w] = TWO_SQRT2 *
            xb[(((size_t)c * SPD + 2 * d) * SPD + 2 * h) * SPD + 2 * w];
    }
    __syncthreads();

    // hidden: exactly 256 (m,w) pairs
    {
        int m = t >> 5;
        int w = t & 31;
        float a = lb1[m];
        const float* wrow = &s_lw1[m * CC];
        #pragma unroll 8
        for (int c = 0; c < CC; c++) a += wrow[c] * s_s[c][w];
        s_hid[m][w] = fmaxf(a, 0.f);
    }
    __syncthreads();

    // gate = sigmoid(g[c] + local[c][w]) -> global gate buffer
    float* gout = g_gate + (((size_t)(b * CC) * SB + d) * SB + h) * SB;
    for (int i = t; i < CC * SB; i += 256) {
        int c = i >> 5;
        int w = i & 31;
        float a = s_lb2[c];
        #pragma unroll
        for (int m = 0; m < MID; m++) a += s_lw2[c * MID + m] * s_hid[m][w];
        a += s_g[c];
        gout[(size_t)c * (SB * SB * SB) + w] = 1.0f / (1.0f + __expf(-a));
    }
}

// ---------------------------------------------------------------------------
// Kernel 4: pure streaming blend. One thread = 2 adjacent 2x2x2 blocks
// (one float4 span along w). 16384 uniform CTAs, no smem.
// out = w*x + (1-w)*block_mean
// ---------------------------------------------------------------------------
__global__ __launch_bounds__(256) void k_blend(const float* __restrict__ x,
                                               float* __restrict__ out) {
    unsigned tid = blockIdx.x * 256u + threadIdx.x;   // 0 .. 4194303
    int w4 = tid & 15;            // float4 index along w (16 per row)
    int h  = (tid >> 4) & 31;     // h-block
    int d  = (tid >> 9) & 31;     // d-block
    int bc = tid >> 14;           // 0..255  (b*128 + c)

    size_t base = ((size_t)bc * SPD + 2 * d) * (SPD * SPD)
                + (size_t)(2 * h) * SPD + 4 * w4;

    float4 r00 = __ldcs((const float4*)(x + base));
    float4 r01 = __ldcs((const float4*)(x + base + SPD));
    float4 r10 = __ldcs((const float4*)(x + base + SPD * SPD));
    float4 r11 = __ldcs((const float4*)(x + base + SPD * SPD + SPD));

    float2 g = *(const float2*)(g_gate + (((size_t)bc * SB + d) * SB + h) * SB + 2 * w4);

    float m0 = (r00.x + r00.y + r01.x + r01.y + r10.x + r10.y + r11.x + r11.y) * 0.125f;
    float m1 = (r00.z + r00.w + r01.z + r01.w + r10.z + r10.w + r11.z + r11.w) * 0.125f;
    float om0 = (1.0f - g.x) * m0;
    float om1 = (1.0f - g.y) * m1;

    r00.x = fmaf(g.x, r00.x, om0); r00.y = fmaf(g.x, r00.y, om0);
    r01.x = fmaf(g.x, r01.x, om0); r01.y = fmaf(g.x, r01.y, om0);
    r10.x = fmaf(g.x, r10.x, om0); r10.y = fmaf(g.x, r10.y, om0);
    r11.x = fmaf(g.x, r11.x, om0); r11.y = fmaf(g.x, r11.y, om0);
    r00.z = fmaf(g.y, r00.z, om1); r00.w = fmaf(g.y, r00.w, om1);
    r01.z = fmaf(g.y, r01.z, om1); r01.w = fmaf(g.y, r01.w, om1);
    r10.z = fmaf(g.y, r10.z, om1); r10.w = fmaf(g.y, r10.w, om1);
    r11.z = fmaf(g.y, r11.z, om1); r11.w = fmaf(g.y, r11.w, om1);

    __stcs((float4*)(out + base),                   r00);
    __stcs((float4*)(out + base + SPD),             r01);
    __stcs((float4*)(out + base + SPD * SPD),       r10);
    __stcs((float4*)(out + base + SPD * SPD + SPD), r11);
}

// ---------------------------------------------------------------------------
extern "C" void kernel_launch(void* const* d_in, const int* in_sizes, int n_in,
                              void* d_out, int out_size) {
    const float* x   = (const float*)d_in[0];
    const float* gw1 = (const float*)d_in[1];
    const float* gb1 = (const float*)d_in[2];
    const float* gw2 = (const float*)d_in[3];
    const float* gb2 = (const float*)d_in[4];
    const float* lw1 = (const float*)d_in[5];
    const float* lb1 = (const float*)d_in[6];
    const float* lw2 = (const float*)d_in[7];
    const float* lb2 = (const float*)d_in[8];
    float* out = (float*)d_out;

    k_gap<<<2 * CC * 8, 256>>>(x);
    k_gmlp<<<2, 128>>>(gw1, gb1, gw2, gb2);
    k_gate<<<2 * SB * SB, 256>>>(x, lw1, lb1, lw2, lb2);
    k_blend<<<16384, 256>>>(x, out);
}